// round 4
// baseline (speedup 1.0000x reference)
#include <cuda_runtime.h>

#define BB 64
#define CC 3
#define RR 64
#define CL 64
#define EE 64
#define HH 32
#define LL 3
#define VV 258
#define GG 96   // 3*H

// ---------------- scratch (device globals; no allocation) ----------------
__device__ float g_giemb[CC * VV * GG];          // folded Wih0[:, :64] @ embed  : [c][v][g]
__device__ float g_wpk[CC * 192 * 128];          // packed per-thread weight rows
__device__ float g_bpk[CC * 192 * 4];            // packed per-thread biases
__device__ float g_hid[(size_t)BB * CC * RR * CL * HH];  // all hidden outputs (100.7 MB)

// ---------------- precompute kernels ----------------
__global__ void prep_giemb(const float* __restrict__ Wih0, const float* __restrict__ embed) {
    int idx = blockIdx.x * blockDim.x + threadIdx.x;
    if (idx >= CC * VV * GG) return;
    int c = idx / (VV * GG);
    int rem = idx % (VV * GG);
    int v = rem / GG;
    int g = rem % GG;
    const float* wr = Wih0 + (c * GG + g) * (EE + 1);
    const float* em = embed + (c * VV + v) * EE;
    float acc = 0.f;
#pragma unroll
    for (int e = 0; e < EE; e++) acc += wr[e] * em[e];
    g_giemb[idx] = acc;
}

// Packed weights layout per (c, thread t in [0,192), slot s in [0,4), k in [0,32)):
//  role A (t<96, gate g=t):
//    s0: Wfh[g][k]  = sum_e Wih0[c][g][e] * W_h2e[c][e][k]   (e over 0..64)
//    s1: Wfad[g][k] = sum_e Wih0[c][g][e] * W_ad[c-1][e][k]  (0 for c==0)
//    s2: Wih_rest[c][0][g][k]   (layer 1 input weights)
//    s3: Wih_rest[c][1][g][k]   (layer 2 input weights)
//  role B (t>=96, gate g=t-96):
//    s0: Whh[c][0][g][k], s1: 0, s2: Whh[c][1][g][k], s3: Whh[c][2][g][k]
__global__ void prep_wpk(const float* __restrict__ Wih0, const float* __restrict__ Wih_rest,
                         const float* __restrict__ Whh, const float* __restrict__ W_h2e,
                         const float* __restrict__ W_ad) {
    int idx = blockIdx.x * blockDim.x + threadIdx.x;
    if (idx >= CC * 192 * 128) return;
    int c = idx / (192 * 128);
    int rem = idx % (192 * 128);
    int t = rem / 128;
    int j = rem % 128;
    int s = j / 32;
    int k = j % 32;
    float val = 0.f;
    if (t < 96) {
        int g = t;
        if (s == 0) {
            const float* wr = Wih0 + (c * GG + g) * (EE + 1);
            for (int e = 0; e <= EE; e++)
                val += wr[e] * W_h2e[(c * (EE + 1) + e) * HH + k];
        } else if (s == 1) {
            if (c > 0) {
                const float* wr = Wih0 + (c * GG + g) * (EE + 1);
                for (int e = 0; e <= EE; e++)
                    val += wr[e] * W_ad[((c - 1) * (EE + 1) + e) * HH + k];
            }
        } else {
            int l = s - 2;  // 0 or 1 -> Wih_rest layer index
            val = Wih_rest[((c * (LL - 1) + l) * GG + g) * HH + k];
        }
    } else {
        int g = t - 96;
        if (s == 0) val = Whh[((c * LL + 0) * GG + g) * HH + k];
        else if (s == 1) val = 0.f;
        else val = Whh[((c * LL + (s - 1)) * GG + g) * HH + k];
    }
    g_wpk[idx] = val;
}

// Packed biases: role A: {bf, pvec, bih[l=1], bih[l=2]}  role B: {bhh[0], 0, bhh[1], bhh[2]}
//  bf   = bih[c][0][g] + sum_e Wih0[c][g][e]*(b_h2e[c][e] + (c>0 ? b_ad[c-1][e] : 0))
//  pvec = Wih0[c][g][64]   (row-position coefficient)
__global__ void prep_bpk(const float* __restrict__ Wih0, const float* __restrict__ bih,
                         const float* __restrict__ bhh, const float* __restrict__ b_h2e,
                         const float* __restrict__ b_ad) {
    int idx = blockIdx.x * blockDim.x + threadIdx.x;
    if (idx >= CC * 192 * 4) return;
    int c = idx / (192 * 4);
    int rem = idx % (192 * 4);
    int t = rem / 4;
    int s = rem % 4;
    float val = 0.f;
    if (t < 96) {
        int g = t;
        if (s == 0) {
            val = bih[(c * LL + 0) * GG + g];
            const float* wr = Wih0 + (c * GG + g) * (EE + 1);
            for (int e = 0; e <= EE; e++) {
                float bb = b_h2e[c * (EE + 1) + e];
                if (c > 0) bb += b_ad[(c - 1) * (EE + 1) + e];
                val += wr[e] * bb;
            }
        } else if (s == 1) {
            val = Wih0[(c * GG + g) * (EE + 1) + EE];
        } else {
            val = bih[(c * LL + (s - 1)) * GG + g];
        }
    } else {
        int g = t - 96;
        if (s == 0) val = bhh[(c * LL + 0) * GG + g];
        else if (s == 1) val = 0.f;
        else val = bhh[(c * LL + (s - 1)) * GG + g];
    }
    g_bpk[idx] = val;
}

// ---------------- RNN kernel ----------------
__device__ __forceinline__ float sigm_f(float x) {
    return __fdividef(1.f, 1.f + __expf(-x));
}
__device__ __forceinline__ float tanh_f(float x) {
    float e = __expf(-2.f * x);
    return __fdividef(2.f, 1.f + e) - 1.f;
}

__global__ void __launch_bounds__(192, 1) rnn_kernel(const int* __restrict__ x) {
    const int b = blockIdx.x;
    const int tid = threadIdx.x;
    const bool isA = tid < 96;
    const int g = isA ? tid : tid - 96;

    __shared__ __align__(16) float s_prev[CL][HH];  // previous row outputs (in-place updated)
    __shared__ __align__(16) float s_pout[CL][HH];  // previous channel outputs for this row
    __shared__ __align__(16) float s_h[LL][HH];     // per-layer hidden state
    __shared__ float s_a[GG];                        // gi gates
    __shared__ float s_b[GG];                        // gh gates
    __shared__ int s_idx[CL];

    for (int c = 0; c < CC; c++) {
        // per-thread register weights: slots [0..7]=s0, [8..15]=s1, [16..23]=s2, [24..31]=s3
        float4 w[32];
        const float4* wp = reinterpret_cast<const float4*>(g_wpk) + ((size_t)(c * 192 + tid)) * 32;
#pragma unroll
        for (int i = 0; i < 32; i++) w[i] = wp[i];
        const float4 bp = reinterpret_cast<const float4*>(g_bpk)[c * 192 + tid];

        const float* giC = g_giemb + (size_t)c * VV * GG;
        const float* poutG = g_hid + (size_t)(b * CC + (c > 0 ? c - 1 : 0)) * (RR * CL * HH);
        float* hidG = g_hid + (size_t)(b * CC + c) * (RR * CL * HH);

        // zero prev-row buffer (row 0 sees zero init hidden)
        for (int i = tid; i < CL * HH; i += 192) (&s_prev[0][0])[i] = 0.f;

        for (int r = 0; r < RR; r++) {
            const float pos = (float)r * (1.f / 32.f) - 1.f;
            const float bias0 = bp.x + bp.y * pos;  // role B: bp.y == 0
            if (tid < CL) s_idx[tid] = x[(((b * CC) + c) * RR + r) * CL + tid];
            if (c > 0) {
                const float* src = poutG + (size_t)r * CL * HH;
                for (int i = tid; i < CL * HH; i += 192) (&s_pout[0][0])[i] = src[i];
            }
            if (tid < LL * HH) (&s_h[0][0])[tid] = 0.f;
            __syncthreads();

            float gie = isA ? giC[s_idx[0] * GG + g] : 0.f;

            for (int t = 0; t < CL; t++) {
                // ---------- phase 0: A computes gi0 (Wfh*prev + Wfad*pout + giemb + bias),
                //                     B computes gh0 (Whh0 * h0) ----------
                {
                    const float* hin_s = isA ? &s_prev[t][0] : &s_h[0][0];
                    const float4* hin = reinterpret_cast<const float4*>(hin_s);
                    float acc = bias0;
#pragma unroll
                    for (int i = 0; i < 8; i++) {
                        float4 h4 = hin[i];
                        acc = fmaf(w[i].x, h4.x, acc);
                        acc = fmaf(w[i].y, h4.y, acc);
                        acc = fmaf(w[i].z, h4.z, acc);
                        acc = fmaf(w[i].w, h4.w, acc);
                    }
                    if (isA) {
                        acc += gie;
                        if (c > 0) {
                            const float4* pp = reinterpret_cast<const float4*>(&s_pout[t][0]);
#pragma unroll
                            for (int i = 0; i < 8; i++) {
                                float4 h4 = pp[i];
                                acc = fmaf(w[8 + i].x, h4.x, acc);
                                acc = fmaf(w[8 + i].y, h4.y, acc);
                                acc = fmaf(w[8 + i].z, h4.z, acc);
                                acc = fmaf(w[8 + i].w, h4.w, acc);
                            }
                        }
                        s_a[g] = acc;
                    } else {
                        s_b[g] = acc;
                    }
                }
                // prefetch next column's giemb gather (independent of serial chain)
                float gie_n = (isA && (t + 1 < CL)) ? giC[s_idx[t + 1] * GG + g] : 0.f;
                __syncthreads();
                if (tid < 32) {  // GRU cell layer 0
                    float rg = sigm_f(s_a[tid] + s_b[tid]);
                    float zg = sigm_f(s_a[32 + tid] + s_b[32 + tid]);
                    float ng = tanh_f(s_a[64 + tid] + rg * s_b[64 + tid]);
                    float h0 = s_h[0][tid];
                    s_h[0][tid] = ng + zg * (h0 - ng);
                }
                __syncthreads();

                // ---------- phase 1 ----------
                {
                    const float* hin_s = isA ? &s_h[0][0] : &s_h[1][0];
                    const float4* hin = reinterpret_cast<const float4*>(hin_s);
                    float acc = bp.z;
#pragma unroll
                    for (int i = 0; i < 8; i++) {
                        float4 h4 = hin[i];
                        acc = fmaf(w[16 + i].x, h4.x, acc);
                        acc = fmaf(w[16 + i].y, h4.y, acc);
                        acc = fmaf(w[16 + i].z, h4.z, acc);
                        acc = fmaf(w[16 + i].w, h4.w, acc);
                    }
                    if (isA) s_a[g] = acc; else s_b[g] = acc;
                }
                __syncthreads();
                if (tid < 32) {  // GRU cell layer 1
                    float rg = sigm_f(s_a[tid] + s_b[tid]);
                    float zg = sigm_f(s_a[32 + tid] + s_b[32 + tid]);
                    float ng = tanh_f(s_a[64 + tid] + rg * s_b[64 + tid]);
                    float h1 = s_h[1][tid];
                    s_h[1][tid] = ng + zg * (h1 - ng);
                }
                __syncthreads();

                // ---------- phase 2 ----------
                {
                    const float* hin_s = isA ? &s_h[1][0] : &s_h[2][0];
                    const float4* hin = reinterpret_cast<const float4*>(hin_s);
                    float acc = bp.w;
#pragma unroll
                    for (int i = 0; i < 8; i++) {
                        float4 h4 = hin[i];
                        acc = fmaf(w[24 + i].x, h4.x, acc);
                        acc = fmaf(w[24 + i].y, h4.y, acc);
                        acc = fmaf(w[24 + i].z, h4.z, acc);
                        acc = fmaf(w[24 + i].w, h4.w, acc);
                    }
                    if (isA) s_a[g] = acc; else s_b[g] = acc;
                }
                __syncthreads();
                if (tid < 32) {  // GRU cell layer 2 + emit output hidden
                    float rg = sigm_f(s_a[tid] + s_b[tid]);
                    float zg = sigm_f(s_a[32 + tid] + s_b[32 + tid]);
                    float ng = tanh_f(s_a[64 + tid] + rg * s_b[64 + tid]);
                    float h2 = s_h[2][tid];
                    float hn = ng + zg * (h2 - ng);
                    s_h[2][tid] = hn;
                    s_prev[t][tid] = hn;  // becomes prev-row input for next row
                    hidG[((size_t)r * CL + t) * HH + tid] = hn;
                }
                gie = gie_n;
                __syncthreads();
            }
        }
        __syncthreads();
    }
}

// ---------------- output projection: out[p][v] = sum_k h[p][k]*Wout[v][k] + bout[v] ----------------
__global__ void __launch_bounds__(256, 2) proj_kernel(const float* __restrict__ Wout,
                                                      const float* __restrict__ bout,
                                                      float* __restrict__ out) {
    __shared__ float Ws[32][264];  // Ws[k][v]
    __shared__ float hs[32][72];   // hs[k][p]
    __shared__ float bs[264];

    const int tid = threadIdx.x;
    const size_t p0 = (size_t)blockIdx.x * 64;

    for (int i = tid; i < VV * HH; i += 256) {
        int v = i >> 5, k = i & 31;
        Ws[k][v] = Wout[i];
    }
    if (tid < 256) bs[tid] = (tid < VV) ? bout[tid] : 0.f;
    if (tid < 2) bs[256 + tid] = bout[256 + tid];
    {
        const float* hsrc = g_hid + p0 * HH;
        for (int i = tid; i < 64 * HH; i += 256) {
            int p = i >> 5, k = i & 31;
            hs[k][p] = hsrc[i];
        }
    }
    __syncthreads();

    const int tv = tid & 31;   // v-tile: 8 consecutive v
    const int tp = tid >> 5;   // p-tile: 8 consecutive positions
    const int vb = tv * 8, pb = tp * 8;

    float acc[8][8];
#pragma unroll
    for (int pi = 0; pi < 8; pi++)
#pragma unroll
        for (int vi = 0; vi < 8; vi++) acc[pi][vi] = 0.f;

#pragma unroll 4
    for (int k = 0; k < 32; k++) {
        float4 wa = *reinterpret_cast<const float4*>(&Ws[k][vb]);
        float4 wb = *reinterpret_cast<const float4*>(&Ws[k][vb + 4]);
        float4 ha = *reinterpret_cast<const float4*>(&hs[k][pb]);
        float4 hb = *reinterpret_cast<const float4*>(&hs[k][pb + 4]);
        float hv[8] = {ha.x, ha.y, ha.z, ha.w, hb.x, hb.y, hb.z, hb.w};
        float wv[8] = {wa.x, wa.y, wa.z, wa.w, wb.x, wb.y, wb.z, wb.w};
#pragma unroll
        for (int pi = 0; pi < 8; pi++)
#pragma unroll
            for (int vi = 0; vi < 8; vi++)
                acc[pi][vi] = fmaf(hv[pi], wv[vi], acc[pi][vi]);
    }

#pragma unroll
    for (int pi = 0; pi < 8; pi++) {
        size_t base = (p0 + pb + pi) * VV + vb;
#pragma unroll
        for (int vi = 0; vi < 8; vi += 2) {
            float2 o;
            o.x = acc[pi][vi] + bs[vb + vi];
            o.y = acc[pi][vi + 1] + bs[vb + vi + 1];
            *reinterpret_cast<float2*>(&out[base + vi]) = o;
        }
    }

    // tail columns v = 256, 257
    if (tid < 128) {
        int p = tid >> 1;
        int v = 256 + (tid & 1);
        float a = bs[v];
#pragma unroll
        for (int k = 0; k < 32; k++) a = fmaf(hs[k][p], Ws[k][v], a);
        out[(p0 + p) * VV + v] = a;
    }
}

// ---------------- launcher ----------------
extern "C" void kernel_launch(void* const* d_in, const int* in_sizes, int n_in,
                              void* d_out, int out_size) {
    const int* x = (const int*)d_in[0];
    const float* embed = (const float*)d_in[1];
    const float* Wih0 = (const float*)d_in[2];
    const float* Wih_rest = (const float*)d_in[3];
    const float* Whh = (const float*)d_in[4];
    const float* bih = (const float*)d_in[5];
    const float* bhh = (const float*)d_in[6];
    const float* W_h2e = (const float*)d_in[7];
    const float* b_h2e = (const float*)d_in[8];
    const float* W_ad = (const float*)d_in[9];
    const float* b_ad = (const float*)d_in[10];
    const float* W_out = (const float*)d_in[11];
    const float* b_out = (const float*)d_in[12];
    float* out = (float*)d_out;

    prep_giemb<<<(CC * VV * GG + 127) / 128, 128>>>(Wih0, embed);
    prep_wpk<<<(CC * 192 * 128 + 127) / 128, 128>>>(Wih0, Wih_rest, Whh, W_h2e, W_ad);
    prep_bpk<<<(CC * 192 * 4 + 127) / 128, 128>>>(Wih0, bih, bhh, b_h2e, b_ad);
    rnn_kernel<<<BB, 192>>>(x);
    proj_kernel<<<(BB * CC * RR * CL) / 64, 256>>>(W_out, b_out, out);
}

// round 5
// speedup vs baseline: 1.7525x; 1.7525x over previous
#include <cuda_runtime.h>

#define BB 64
#define CC 3
#define RR 64
#define CL 64
#define EE 64
#define HH 32
#define LL 3
#define VV 258
#define GG 96   // 3*H

typedef unsigned long long u64;

// ---------------- scratch (device globals; no allocation) ----------------
__device__ float g_giemb[CC * VV * GG];               // [c][v][g] = Wih0[:, :64] @ embed
__device__ float g_wpk[CC * 288 * 96];                // per-thread packed rows: wi[32], wh[32], wq[32]
__device__ float g_bpk[CC * 288 * 4];                 // per-thread bias: (bi, bh, pv, 0)
__device__ float g_hid[(size_t)BB * CC * RR * CL * HH];  // all hidden outputs

// ---------------- helpers ----------------
#define FMA2(acc, a, b) asm("fma.rn.f32x2 %0, %1, %2, %0;" : "+l"(acc) : "l"(a), "l"(b))

__device__ __forceinline__ float sum2(u64 a) {
    float lo = __uint_as_float((unsigned)(a & 0xffffffffull));
    float hi = __uint_as_float((unsigned)(a >> 32));
    return lo + hi;
}
__device__ __forceinline__ void cpa16(void* dst, const void* src) {
    unsigned sd = (unsigned)__cvta_generic_to_shared(dst);
    asm volatile("cp.async.ca.shared.global [%0], [%1], 16;" :: "r"(sd), "l"(src) : "memory");
}
__device__ __forceinline__ float sigm_f(float x) {
    return __fdividef(1.f, 1.f + __expf(-x));
}
__device__ __forceinline__ float tanh_f(float x) {
    float e = __expf(-2.f * x);
    return __fdividef(2.f, 1.f + e) - 1.f;
}

// ---------------- precompute kernels ----------------
__global__ void prep_giemb(const float* __restrict__ Wih0, const float* __restrict__ embed) {
    int idx = blockIdx.x * blockDim.x + threadIdx.x;
    if (idx >= CC * VV * GG) return;
    int c = idx / (VV * GG);
    int rem = idx % (VV * GG);
    int v = rem / GG;
    int g = rem % GG;
    const float* wr = Wih0 + (c * GG + g) * (EE + 1);
    const float* em = embed + (c * VV + v) * EE;
    float acc = 0.f;
#pragma unroll
    for (int e = 0; e < EE; e++) acc += wr[e] * em[e];
    g_giemb[idx] = acc;
}

// Per (c, thread t in [0,288)): l = t/96, g = t%96. 96 floats:
//   [0:32)  wi : l==0 -> Wfh[g]  (Wih0 @ W_h2e); l>=1 -> Wih_rest[c][l-1][g]
//   [32:64) wh : Whh[c][l][g]
//   [64:96) wq : l==0 && c>0 -> Wfad[g] (Wih0 @ W_ad); else 0
__global__ void prep_wpk2(const float* __restrict__ Wih0, const float* __restrict__ Wih_rest,
                          const float* __restrict__ Whh, const float* __restrict__ W_h2e,
                          const float* __restrict__ W_ad) {
    int idx = blockIdx.x * blockDim.x + threadIdx.x;
    if (idx >= CC * 288 * 96) return;
    int c = idx / (288 * 96);
    int rem = idx % (288 * 96);
    int t = rem / 96;
    int j = rem % 96;
    int s = j / 32;
    int k = j % 32;
    int l = t / 96;
    int g = t % 96;
    float val = 0.f;
    if (s == 0) {
        if (l == 0) {
            const float* wr = Wih0 + (c * GG + g) * (EE + 1);
            for (int e = 0; e <= EE; e++)
                val += wr[e] * W_h2e[(c * (EE + 1) + e) * HH + k];
        } else {
            val = Wih_rest[((c * (LL - 1) + (l - 1)) * GG + g) * HH + k];
        }
    } else if (s == 1) {
        val = Whh[((c * LL + l) * GG + g) * HH + k];
    } else {
        if (l == 0 && c > 0) {
            const float* wr = Wih0 + (c * GG + g) * (EE + 1);
            for (int e = 0; e <= EE; e++)
                val += wr[e] * W_ad[((c - 1) * (EE + 1) + e) * HH + k];
        }
    }
    g_wpk[idx] = val;
}

__global__ void prep_bpk2(const float* __restrict__ Wih0, const float* __restrict__ bih,
                          const float* __restrict__ bhh, const float* __restrict__ b_h2e,
                          const float* __restrict__ b_ad) {
    int idx = blockIdx.x * blockDim.x + threadIdx.x;
    if (idx >= CC * 288) return;
    int c = idx / 288;
    int t = idx % 288;
    int l = t / 96;
    int g = t % 96;
    float bi, bh, pv;
    if (l == 0) {
        bi = bih[(c * LL + 0) * GG + g];
        const float* wr = Wih0 + (c * GG + g) * (EE + 1);
        for (int e = 0; e <= EE; e++) {
            float bb = b_h2e[c * (EE + 1) + e];
            if (c > 0) bb += b_ad[(c - 1) * (EE + 1) + e];
            bi += wr[e] * bb;
        }
        pv = Wih0[(c * GG + g) * (EE + 1) + EE];
    } else {
        bi = bih[(c * LL + l) * GG + g];
        pv = 0.f;
    }
    bh = bhh[(c * LL + l) * GG + g];
    g_bpk[idx * 4 + 0] = bi;
    g_bpk[idx * 4 + 1] = bh;
    g_bpk[idx * 4 + 2] = pv;
    g_bpk[idx * 4 + 3] = 0.f;
}

// ---------------- pipelined RNN kernel ----------------
// 288 threads = 3 layer groups x 96 gates. Step s: group l works column t = s - l.
// Gates phase: thread (l,g) computes gi (input side) and gh (hidden side) dot products.
// Cell phase: threads g<32 of each group update hidden unit g of layer l.
__global__ void __launch_bounds__(288, 1) rnn_kernel(const int* __restrict__ x) {
    const int b = blockIdx.x;
    const int tid = threadIdx.x;
    const int l = tid / 96;
    const int g = tid % 96;

    __shared__ __align__(16) float s_h[LL][HH];          // layer hiddens (single buffer)
    __shared__ float s_a[LL][GG];                         // gi sums
    __shared__ float s_b[LL][GG];                         // gh sums
    __shared__ __align__(16) float s_row[2][CL][HH];      // prev/cur row layer-2 outputs
    __shared__ __align__(16) float s_pout[2][CL][HH];     // prev-channel outputs (double buf)
    __shared__ __align__(16) int s_idx[2][CL];

    for (int c = 0; c < CC; c++) {
        // load per-thread weights as packed f32x2 pairs
        const ulonglong2* wv =
            reinterpret_cast<const ulonglong2*>(g_wpk + ((size_t)(c * 288 + tid)) * 96);
        ulonglong2 wi[8], wh[8], wq[8];
#pragma unroll
        for (int i = 0; i < 8; i++) wi[i] = wv[i];
#pragma unroll
        for (int i = 0; i < 8; i++) wh[i] = wv[8 + i];
#pragma unroll
        for (int i = 0; i < 8; i++) wq[i] = wv[16 + i];
        const float4 bias = reinterpret_cast<const float4*>(g_bpk)[c * 288 + tid];

        const float* giC = g_giemb + (size_t)c * VV * GG;
        const float* poutG = g_hid + (size_t)(b * CC + (c > 0 ? c - 1 : 0)) * (RR * CL * HH);
        float* hidG = g_hid + (size_t)(b * CC + c) * (RR * CL * HH);
        const int* xc = x + (size_t)(b * CC + c) * (RR * CL);

        // zero read rowbuf (row 0 reads buffer 0 = zeros)
        for (int i = tid; i < CL * HH; i += 288) (&s_row[0][0][0])[i] = 0.f;

        // prefetch row 0 (pout + idx) into buffer 0
        if (c > 0) {
            const char* src = (const char*)poutG;
            char* dst = (char*)&s_pout[0][0][0];
            for (int i = tid; i < 512; i += 288) cpa16(dst + i * 16, src + i * 16);
        }
        if (tid < 16) cpa16((char*)&s_idx[0][0] + tid * 16, (const char*)xc + tid * 16);
        asm volatile("cp.async.commit_group;" ::: "memory");

        for (int r = 0; r < RR; r++) {
            const int rb = r & 1, wb = rb ^ 1;
            if (g < HH) s_h[l][g] = 0.f;  // reset layer hiddens (all 3 groups)

            // prefetch row r+1 into buffer wb
            if (r + 1 < RR) {
                if (c > 0) {
                    const char* src = (const char*)(poutG + (size_t)(r + 1) * CL * HH);
                    char* dst = (char*)&s_pout[wb][0][0];
                    for (int i = tid; i < 512; i += 288) cpa16(dst + i * 16, src + i * 16);
                }
                if (tid < 16)
                    cpa16((char*)&s_idx[wb][0] + tid * 16,
                          (const char*)(xc + (r + 1) * CL) + tid * 16);
            }
            asm volatile("cp.async.commit_group;" ::: "memory");
            asm volatile("cp.async.wait_group 1;" ::: "memory");
            __syncthreads();  // row r data + s_h zero visible

            const float pos = (float)r * (1.f / 32.f) - 1.f;
            const float bi0 = bias.x + bias.z * pos;
            float gie = 0.f;
            if (l == 0) gie = giC[s_idx[rb][0] * GG + g];

            for (int s = 0; s < CL + LL - 1; s++) {
                const int t = s - l;                 // warp-uniform (96 = 3 warps/group)
                const bool act = ((unsigned)t < (unsigned)CL);
                if (act) {
                    // gh = Whh_l . h_l  (prev column's h)
                    u64 A0 = 0, A1 = 0;
                    const ulonglong2* hv = reinterpret_cast<const ulonglong2*>(&s_h[l][0]);
#pragma unroll
                    for (int i = 0; i < 8; i++) {
                        ulonglong2 h4 = hv[i];
                        FMA2(A0, wh[i].x, h4.x);
                        FMA2(A1, wh[i].y, h4.y);
                    }
                    // gi = Wi . input  (l==0: prev-row h2; l>=1: h_{l-1})
                    u64 B0 = 0, B1 = 0;
                    const ulonglong2* iv =
                        (l == 0) ? reinterpret_cast<const ulonglong2*>(&s_row[rb][t][0])
                                 : reinterpret_cast<const ulonglong2*>(&s_h[l - 1][0]);
#pragma unroll
                    for (int i = 0; i < 8; i++) {
                        ulonglong2 h4 = iv[i];
                        FMA2(B0, wi[i].x, h4.x);
                        FMA2(B1, wi[i].y, h4.y);
                    }
                    float accI;
                    if (l == 0) {
                        if (c > 0) {
                            const ulonglong2* pv2 =
                                reinterpret_cast<const ulonglong2*>(&s_pout[rb][t][0]);
#pragma unroll
                            for (int i = 0; i < 8; i++) {
                                ulonglong2 h4 = pv2[i];
                                FMA2(B0, wq[i].x, h4.x);
                                FMA2(B1, wq[i].y, h4.y);
                            }
                        }
                        accI = sum2(B0) + sum2(B1) + bi0 + gie;
                    } else {
                        accI = sum2(B0) + sum2(B1) + bias.x;
                    }
                    s_a[l][g] = accI;
                    s_b[l][g] = sum2(A0) + sum2(A1) + bias.y;
                }
                // prefetch next column's embedding-gather (group 0 only)
                if (l == 0 && s + 1 < CL) gie = giC[s_idx[rb][s + 1] * GG + g];
                __syncthreads();

                if (g < HH && act) {  // GRU cell for layer l, unit g
                    float ar = s_a[l][g], az = s_a[l][g + 32], an = s_a[l][g + 64];
                    float br = s_b[l][g], bz = s_b[l][g + 32], bn = s_b[l][g + 64];
                    float rg = sigm_f(ar + br);
                    float zg = sigm_f(az + bz);
                    float ng = tanh_f(an + rg * bn);
                    float ho = s_h[l][g];
                    float hn = ng + zg * (ho - ng);
                    s_h[l][g] = hn;
                    if (l == 2) {
                        s_row[wb][t][g] = hn;                    // feeds next row
                        hidG[((size_t)r * CL + t) * HH + g] = hn;  // feeds pout + projection
                    }
                }
                __syncthreads();
            }
        }
        __syncthreads();
    }
}

// ---------------- output projection: out[p][v] = sum_k h[p][k]*Wout[v][k] + bout[v] ----------------
__global__ void __launch_bounds__(256, 2) proj_kernel(const float* __restrict__ Wout,
                                                      const float* __restrict__ bout,
                                                      float* __restrict__ out) {
    __shared__ float Ws[32][264];  // Ws[k][v]
    __shared__ float hs[32][72];   // hs[k][p]
    __shared__ float bs[264];

    const int tid = threadIdx.x;
    const size_t p0 = (size_t)blockIdx.x * 64;

    for (int i = tid; i < VV * HH; i += 256) {
        int v = i >> 5, k = i & 31;
        Ws[k][v] = Wout[i];
    }
    if (tid < 256) bs[tid] = (tid < VV) ? bout[tid] : 0.f;
    if (tid < 2) bs[256 + tid] = bout[256 + tid];
    {
        const float* hsrc = g_hid + p0 * HH;
        for (int i = tid; i < 64 * HH; i += 256) {
            int p = i >> 5, k = i & 31;
            hs[k][p] = hsrc[i];
        }
    }
    __syncthreads();

    const int tv = tid & 31;
    const int tp = tid >> 5;
    const int vb = tv * 8, pb = tp * 8;

    float acc[8][8];
#pragma unroll
    for (int pi = 0; pi < 8; pi++)
#pragma unroll
        for (int vi = 0; vi < 8; vi++) acc[pi][vi] = 0.f;

#pragma unroll 4
    for (int k = 0; k < 32; k++) {
        float4 wa = *reinterpret_cast<const float4*>(&Ws[k][vb]);
        float4 wb = *reinterpret_cast<const float4*>(&Ws[k][vb + 4]);
        float4 ha = *reinterpret_cast<const float4*>(&hs[k][pb]);
        float4 hb = *reinterpret_cast<const float4*>(&hs[k][pb + 4]);
        float hv[8] = {ha.x, ha.y, ha.z, ha.w, hb.x, hb.y, hb.z, hb.w};
        float wv[8] = {wa.x, wa.y, wa.z, wa.w, wb.x, wb.y, wb.z, wb.w};
#pragma unroll
        for (int pi = 0; pi < 8; pi++)
#pragma unroll
            for (int vi = 0; vi < 8; vi++)
                acc[pi][vi] = fmaf(hv[pi], wv[vi], acc[pi][vi]);
    }

#pragma unroll
    for (int pi = 0; pi < 8; pi++) {
        size_t base = (p0 + pb + pi) * VV + vb;
#pragma unroll
        for (int vi = 0; vi < 8; vi += 2) {
            float2 o;
            o.x = acc[pi][vi] + bs[vb + vi];
            o.y = acc[pi][vi + 1] + bs[vb + vi + 1];
            *reinterpret_cast<float2*>(&out[base + vi]) = o;
        }
    }

    if (tid < 128) {
        int p = tid >> 1;
        int v = 256 + (tid & 1);
        float a = bs[v];
#pragma unroll
        for (int k = 0; k < 32; k++) a = fmaf(hs[k][p], Ws[k][v], a);
        out[(p0 + p) * VV + v] = a;
    }
}

// ---------------- launcher ----------------
extern "C" void kernel_launch(void* const* d_in, const int* in_sizes, int n_in,
                              void* d_out, int out_size) {
    const int* x = (const int*)d_in[0];
    const float* embed = (const float*)d_in[1];
    const float* Wih0 = (const float*)d_in[2];
    const float* Wih_rest = (const float*)d_in[3];
    const float* Whh = (const float*)d_in[4];
    const float* bih = (const float*)d_in[5];
    const float* bhh = (const float*)d_in[6];
    const float* W_h2e = (const float*)d_in[7];
    const float* b_h2e = (const float*)d_in[8];
    const float* W_ad = (const float*)d_in[9];
    const float* b_ad = (const float*)d_in[10];
    const float* W_out = (const float*)d_in[11];
    const float* b_out = (const float*)d_in[12];
    float* out = (float*)d_out;

    prep_giemb<<<(CC * VV * GG + 127) / 128, 128>>>(Wih0, embed);
    prep_wpk2<<<(CC * 288 * 96 + 127) / 128, 128>>>(Wih0, Wih_rest, Whh, W_h2e, W_ad);
    prep_bpk2<<<(CC * 288 + 127) / 128, 128>>>(Wih0, bih, bhh, b_h2e, b_ad);
    rnn_kernel<<<BB, 288>>>(x);
    proj_kernel<<<(BB * CC * RR * CL) / 64, 256>>>(W_out, b_out, out);
}